// round 15
// baseline (speedup 1.0000x reference)
#include <cuda_runtime.h>
#include <cuda_bf16.h>
#include <math.h>

#define CM 64
#define NA 512
#define MS 32768
#define KS 5
#define HW 4096
#define CHW 262144
#define NUMEL 2097152.0f
#define FULL 0xffffffffu

typedef unsigned long long u64;

// packed fp32x2 helpers (sm_103a; ptxas never emits these on its own)
#define F32X2_FMA(d, a, b) \
    asm("fma.rn.f32x2 %0, %1, %2, %0;" : "+l"(d) : "l"(a), "l"(b))
#define F32X2_MUL(d, a, b) \
    asm("mul.rn.f32x2 %0, %1, %2;" : "=l"(d) : "l"(a), "l"(b))
#define F32X2_ADD(d, a, b) \
    asm("add.rn.f32x2 %0, %1, %2;" : "=l"(d) : "l"(a), "l"(b))
#define F32X2_DUP(d, x) \
    asm("mov.b64 %0, {%1, %1};" : "=l"(d) : "r"(__float_as_uint(x)))

__device__ __forceinline__ float u64_lo(u64 v) { return __uint_as_float((unsigned)v); }
__device__ __forceinline__ float u64_hi(u64 v) { return __uint_as_float((unsigned)(v >> 32)); }

__device__ float g_DnT[NA * CM];
__device__ float g_G[NA * NA];
__device__ float g_H[(size_t)MS * NA];
__device__ float g_partial[1024];
__device__ unsigned g_count = 0;

// ---------------------------------------------------------------------------
// Kernel 1: FUSED  H = X^T Dn (bids 0..1023)  +  G = Dn^T Dn (bids 1024..1087)
// with in-branch dictionary normalization (no separate k_norm, no g_Dn).
// The 8 gram CTAs with j0==0 also emit g_DnT.
// ---------------------------------------------------------------------------
__global__ __launch_bounds__(256, 2) void k_gg(const float* __restrict__ ze,
                                               const float* __restrict__ dict) {
    __shared__ float S[2 * CM * 128];   // 64KB
    __shared__ float inv[128];

    if (blockIdx.x < 1024) {
        // ---------------- GEMM branch ----------------
        float (*As)[128] = (float (*)[128])S;
        float (*Bs)[128] = (float (*)[128])(S + CM * 128);
        int tx = threadIdx.x & 15, ty = threadIdx.x >> 4;
        int m0 = (blockIdx.x >> 2) * 128, n0 = (blockIdx.x & 3) * 128;
        int bb = m0 >> 12;
        int p0 = m0 & (HW - 1);
        const float* zb = ze + (size_t)bb * CHW + p0;

        // column inverse norms for this 128-wide B tile (c=0..63 order)
        if (threadIdx.x < 128) {
            float s = 0.f;
            #pragma unroll
            for (int c = 0; c < CM; c++) {
                float v = dict[c * NA + n0 + threadIdx.x];
                s += v * v;
            }
            inv[threadIdx.x] = 1.f / fmaxf(sqrtf(s), 1e-10f);
        }
        __syncthreads();

        #pragma unroll
        for (int r = 0; r < 8; r++) {
            int idx = r * 256 + threadIdx.x;
            int kk = idx >> 5, m4 = (idx & 31) << 2;
            *(float4*)&As[kk][m4] = *(const float4*)(zb + (size_t)kk * HW + m4);
            float4 b = *(const float4*)(dict + (size_t)kk * NA + n0 + m4);
            b.x *= inv[m4]; b.y *= inv[m4 + 1]; b.z *= inv[m4 + 2]; b.w *= inv[m4 + 3];
            *(float4*)&Bs[kk][m4] = b;
        }
        __syncthreads();

        u64 acc2[8][4];
        #pragma unroll
        for (int i = 0; i < 8; i++)
            #pragma unroll
            for (int j = 0; j < 4; j++) acc2[i][j] = 0ull;

        #pragma unroll
        for (int k = 0; k < CM; k++) {
            float4 a0 = *(float4*)&As[k][ty * 8];
            float4 a1 = *(float4*)&As[k][ty * 8 + 4];
            ulonglong2 bp0 = *(ulonglong2*)&Bs[k][tx * 8];
            ulonglong2 bp1 = *(ulonglong2*)&Bs[k][tx * 8 + 4];
            float ar[8] = {a0.x, a0.y, a0.z, a0.w, a1.x, a1.y, a1.z, a1.w};
            u64 bp[4] = {bp0.x, bp0.y, bp1.x, bp1.y};
            #pragma unroll
            for (int i = 0; i < 8; i++) {
                u64 ad;
                F32X2_DUP(ad, ar[i]);
                #pragma unroll
                for (int j = 0; j < 4; j++)
                    F32X2_FMA(acc2[i][j], ad, bp[j]);
            }
        }
        #pragma unroll
        for (int i = 0; i < 8; i++) {
            int m = m0 + ty * 8 + i;
            u64* o = (u64*)&g_H[(size_t)m * NA + n0 + tx * 8];
            ulonglong2 s0, s1;
            s0.x = acc2[i][0]; s0.y = acc2[i][1];
            s1.x = acc2[i][2]; s1.y = acc2[i][3];
            *(ulonglong2*)o       = s0;
            *(ulonglong2*)(o + 2) = s1;
        }
    } else {
        // ---------------- GRAM branch ----------------
        int bid2 = blockIdx.x - 1024;
        float (*As)[64] = (float (*)[64])S;
        float (*Bs)[64] = (float (*)[64])(S + CM * 64);
        int i0 = (bid2 >> 3) * 64, j0 = (bid2 & 7) * 64;

        // inv[0..63] = I-tile norms, inv[64..127] = J-tile norms
        if (threadIdx.x < 128) {
            int col = threadIdx.x & 63;
            int n = (threadIdx.x < 64) ? (i0 + col) : (j0 + col);
            float s = 0.f;
            #pragma unroll
            for (int c = 0; c < CM; c++) {
                float v = dict[c * NA + n];
                s += v * v;
            }
            inv[threadIdx.x] = 1.f / fmaxf(sqrtf(s), 1e-10f);
        }
        __syncthreads();

        #pragma unroll
        for (int r = 0; r < 4; r++) {
            int idx = r * 256 + threadIdx.x;
            int c = idx >> 4, m4 = (idx & 15) << 2;
            float4 a = *(const float4*)(dict + (size_t)c * NA + i0 + m4);
            a.x *= inv[m4]; a.y *= inv[m4 + 1]; a.z *= inv[m4 + 2]; a.w *= inv[m4 + 3];
            *(float4*)&As[c][m4] = a;
            float4 b = *(const float4*)(dict + (size_t)c * NA + j0 + m4);
            b.x *= inv[64 + m4]; b.y *= inv[64 + m4 + 1];
            b.z *= inv[64 + m4 + 2]; b.w *= inv[64 + m4 + 3];
            *(float4*)&Bs[c][m4] = b;
        }
        __syncthreads();

        int tx = threadIdx.x & 15, ty = threadIdx.x >> 4;
        u64 acc2[4][2];
        #pragma unroll
        for (int i = 0; i < 4; i++) { acc2[i][0] = 0ull; acc2[i][1] = 0ull; }

        #pragma unroll
        for (int k = 0; k < CM; k++) {
            float4 a = *(float4*)&As[k][ty * 4];
            ulonglong2 b = *(ulonglong2*)&Bs[k][tx * 4];
            float ar[4] = {a.x, a.y, a.z, a.w};
            #pragma unroll
            for (int i = 0; i < 4; i++) {
                u64 ad;
                F32X2_DUP(ad, ar[i]);
                F32X2_FMA(acc2[i][0], ad, b.x);
                F32X2_FMA(acc2[i][1], ad, b.y);
            }
        }
        #pragma unroll
        for (int i = 0; i < 4; i++) {
            ulonglong2 s;
            s.x = acc2[i][0]; s.y = acc2[i][1];
            *(ulonglong2*)&g_G[(size_t)(i0 + ty * 4 + i) * NA + j0 + tx * 4] = s;
        }

        // side output: g_DnT rows i0..i0+63 (j0==0 CTAs only; coalesced gmem)
        if ((bid2 & 7) == 0) {
            for (int idx = threadIdx.x; idx < 64 * CM; idx += 256) {
                int x = idx >> 6, c = idx & 63;
                g_DnT[(size_t)(i0 + x) * CM + c] = As[c][x];
            }
        }
    }
}

// ---------------------------------------------------------------------------
// Kernel 2: OMP + coalesced reconstruction + last-CTA loss finalization.
// ---------------------------------------------------------------------------
__global__ __launch_bounds__(256, 3) void k_omp(const float* __restrict__ ze,
                                                float* __restrict__ out_zdl,
                                                float* __restrict__ out_sup,
                                                float* __restrict__ out_cf,
                                                float* __restrict__ out_loss) {
    __shared__ float rows[8][3][NA];   // 48KB; dead after OMP, reused as tile
    __shared__ unsigned isLast;

    const int lane = threadIdx.x & 31;
    const int wid  = threadIdx.x >> 5;
    const int bid  = gridDim.x - 1 - blockIdx.x;
    const int m0 = bid * 32;

    float recA[4], recB[4];

    #pragma unroll 1
    for (int it = 0; it < 4; it++) {
        const int m = m0 + wid * 4 + it;
        const float* Hb = g_H + (size_t)m * NA;
        const ulonglong2* Hb2 = (const ulonglong2*)Hb;

        u64   h2[8];
        float Lo[10];
        float Linv[5];
        float y[5];
        float gam[5];
        int   sel[5];

        float bv = 0.f;
#pragma unroll
        for (int j = 0; j < 4; j++) {
            ulonglong2 v = __ldg(&Hb2[lane + 32 * j]);
            h2[2 * j] = v.x;
            h2[2 * j + 1] = v.y;
            bv = fmaxf(bv, fabsf(u64_lo(v.x)));
            bv = fmaxf(bv, fabsf(u64_hi(v.x)));
            bv = fmaxf(bv, fabsf(u64_lo(v.y)));
            bv = fmaxf(bv, fabsf(u64_hi(v.y)));
        }

#pragma unroll
        for (int k = 1; k <= KS; k++) {
            float wmax = __uint_as_float(__reduce_max_sync(FULL, __float_as_uint(bv)));
            int cand = 1 << 30;
#pragma unroll
            for (int j = 3; j >= 0; j--) {
                int base = 4 * (lane + 32 * j);
                u64 px = h2[2 * j], py = h2[2 * j + 1];
                if (fabsf(u64_hi(py)) == wmax) cand = base + 3;
                if (fabsf(u64_lo(py)) == wmax) cand = base + 2;
                if (fabsf(u64_hi(px)) == wmax) cand = base + 1;
                if (fabsf(u64_lo(px)) == wmax) cand = base;
            }
            int bi = __reduce_min_sync(FULL, cand);

            const float* Grow = g_G + (size_t)bi * NA;

            ulonglong2 gvv[4];
            if (k < KS) {
                const ulonglong2* Gr2 = (const ulonglong2*)Grow;
#pragma unroll
                for (int j = 0; j < 4; j++) gvv[j] = __ldg(&Gr2[lane + 32 * j]);
            }

            float hbv = __ldg(Hb + bi);

            float Gv[4];
#pragma unroll
            for (int t = 0; t < 3; t++)
                if (t < k - 1) Gv[t] = rows[wid][t][bi];
            if (k == KS) Gv[3] = __ldg(g_G + (size_t)sel[3] * NA + bi);

            if (k > 1) {
                float w[4], ww = 0.f;
#pragma unroll
                for (int i = 0; i < 4; i++) {
                    if (i < k - 1) {
                        float a = Gv[i];
#pragma unroll
                        for (int j = 0; j < 4; j++)
                            if (j < i) a -= Lo[(i - 1) * i / 2 + j] * w[j];
                        if (i > 0) a *= Linv[i];
                        w[i] = a;
                        ww += a * a;
                    }
                }
                const int r = k - 1;
#pragma unroll
                for (int j = 0; j < 4; j++)
                    if (j < r) Lo[(r - 1) * r / 2 + j] = w[j];
                Linv[r] = rsqrtf(fmaxf(1.f - ww, 1e-12f));
            } else {
                Linv[0] = 1.f;
            }
            sel[k - 1] = bi;

            {
                const int i = k - 1;
                float a = hbv;
#pragma unroll
                for (int j = 0; j < 4; j++)
                    if (j < i) a -= Lo[(i - 1) * i / 2 + j] * y[j];
                y[i] = a * Linv[i];
            }

            float g2[5];
#pragma unroll
            for (int i = 4; i >= 0; i--) {
                if (i < k) {
                    float a = y[i];
#pragma unroll
                    for (int j = 0; j < 5; j++)
                        if (j > i && j < k) a -= Lo[(j - 1) * j / 2 + i] * g2[j];
                    g2[i] = a * Linv[i];
                }
            }
            float dg[5];
#pragma unroll
            for (int i = 0; i < 5; i++) {
                if (i < k) {
                    float old = (i < k - 1) ? gam[i] : 0.f;
                    dg[i] = g2[i] - old;
                    gam[i] = g2[i];
                }
            }

            if (k < KS) {
                u64 ndp[4];
#pragma unroll
                for (int t = 0; t < 4; t++)
                    if (t < k) F32X2_DUP(ndp[t], -dg[t]);
                bv = 0.f;
#pragma unroll
                for (int j = 0; j < 4; j++) {
                    int fi = 4 * (lane + 32 * j);
                    if (k - 1 < 3)
                        *(ulonglong2*)&rows[wid][k - 1 < 3 ? k - 1 : 0][fi] = gvv[j];
                    u64 a0, a1;
                    F32X2_MUL(a0, ndp[k - 1], gvv[j].x);
                    F32X2_MUL(a1, ndp[k - 1], gvv[j].y);
#pragma unroll
                    for (int t = 0; t < 3; t++) {
                        if (t < k - 1) {
                            ulonglong2 rv = *(const ulonglong2*)&rows[wid][t][fi];
                            F32X2_FMA(a0, ndp[t], rv.x);
                            F32X2_FMA(a1, ndp[t], rv.y);
                        }
                    }
                    u64 hn0, hn1;
                    F32X2_ADD(hn0, h2[2 * j], a0);
                    F32X2_ADD(hn1, h2[2 * j + 1], a1);
                    h2[2 * j] = hn0;
                    h2[2 * j + 1] = hn1;
                    bv = fmaxf(bv, fabsf(u64_lo(hn0)));
                    bv = fmaxf(bv, fabsf(u64_hi(hn0)));
                    bv = fmaxf(bv, fabsf(u64_lo(hn1)));
                    bv = fmaxf(bv, fabsf(u64_hi(hn1)));
                }
            }
        }

        if (lane < KS) {
            float s = (lane == 0) ? (float)sel[0] :
                      (lane == 1) ? (float)sel[1] :
                      (lane == 2) ? (float)sel[2] :
                      (lane == 3) ? (float)sel[3] : (float)sel[4];
            float c = (lane == 0) ? gam[0] :
                      (lane == 1) ? gam[1] :
                      (lane == 2) ? gam[2] :
                      (lane == 3) ? gam[3] : gam[4];
            out_sup[(size_t)m * KS + lane] = s;
            out_cf[(size_t)m * KS + lane]  = c;
        }

        {
            float r0 = 0.f, r1 = 0.f;
#pragma unroll
            for (int t = 0; t < KS; t++) {
                const float* dn = g_DnT + sel[t] * CM;
                r0 = fmaf(gam[t], __ldg(dn + lane), r0);
                r1 = fmaf(gam[t], __ldg(dn + lane + 32), r1);
            }
            recA[it] = r0;
            recB[it] = r1;
        }
    }

    // ---- alias the dead rows cache as transpose tile + reduction scratch
    __syncthreads();
    float* sm = &rows[0][0][0];
    float (*tile)[33] = (float (*)[33])sm;          // 64 x 33 floats
    float* red = sm + CM * 33;                      // 256 floats
#pragma unroll
    for (int it = 0; it < 4; it++) {
        int s = wid * 4 + it;
        tile[lane][s]      = recA[it];
        tile[lane + 32][s] = recB[it];
    }
    __syncthreads();

    int b  = m0 >> 12;
    int p0 = m0 & (HW - 1);
    int p  = threadIdx.x & 31;
    int cb = threadIdx.x >> 5;
    float err = 0.f;
#pragma unroll
    for (int j = 0; j < 8; j++) {
        int c = cb * 8 + j;
        size_t zi = (size_t)b * CHW + (size_t)c * HW + p0 + p;
        float r = tile[c][p];
        float x = ze[zi];
        float d = r - x;
        err += d * d;
        out_zdl[zi] = r;
    }
    red[threadIdx.x] = err;
    __syncthreads();
    for (int o = 128; o; o >>= 1) {
        if (threadIdx.x < o) red[threadIdx.x] += red[threadIdx.x + o];
        __syncthreads();
    }
    if (threadIdx.x == 0) g_partial[bid] = red[0];

    // ---- last CTA finalizes the loss (deterministic order)
    __threadfence();
    if (threadIdx.x == 0)
        isLast = (atomicAdd(&g_count, 1u) == gridDim.x - 1) ? 1u : 0u;
    __syncthreads();
    if (isLast) {
        float s = 0.f;
        for (int i = threadIdx.x; i < 1024; i += 256) s += g_partial[i];
        red[threadIdx.x] = s;
        __syncthreads();
        for (int o = 128; o; o >>= 1) {
            if (threadIdx.x < o) red[threadIdx.x] += red[threadIdx.x + o];
            __syncthreads();
        }
        if (threadIdx.x == 0) {
            out_loss[0] = 1.25f * red[0] / NUMEL;
            g_count = 0;           // reset for the next graph replay
        }
    }
}

// ---------------------------------------------------------------------------
extern "C" void kernel_launch(void* const* d_in, const int* in_sizes, int n_in,
                              void* d_out, int out_size) {
    const float* ze   = (const float*)d_in[0];
    const float* dict = (const float*)d_in[1];
    float* out = (float*)d_out;
    float* out_zdl  = out;
    float* out_loss = out + 2097152;
    float* out_sup  = out + 2097153;
    float* out_cf   = out + 2097153 + 163840;

    k_gg<<<1024 + 64, 256>>>(ze, dict);
    k_omp<<<MS / 32, 256>>>(ze, out_zdl, out_sup, out_cf, out_loss);
}

// round 16
// speedup vs baseline: 1.0165x; 1.0165x over previous
#include <cuda_runtime.h>
#include <cuda_bf16.h>
#include <math.h>

#define CM 64
#define NA 512
#define MS 32768
#define KS 5
#define HW 4096
#define CHW 262144
#define NUMEL 2097152.0f
#define FULL 0xffffffffu

typedef unsigned long long u64;

// packed fp32x2 helpers (sm_103a; ptxas never emits these on its own)
#define F32X2_FMA(d, a, b) \
    asm("fma.rn.f32x2 %0, %1, %2, %0;" : "+l"(d) : "l"(a), "l"(b))
#define F32X2_MUL(d, a, b) \
    asm("mul.rn.f32x2 %0, %1, %2;" : "=l"(d) : "l"(a), "l"(b))
#define F32X2_ADD(d, a, b) \
    asm("add.rn.f32x2 %0, %1, %2;" : "=l"(d) : "l"(a), "l"(b))
#define F32X2_DUP(d, x) \
    asm("mov.b64 %0, {%1, %1};" : "=l"(d) : "r"(__float_as_uint(x)))

// cp.async helpers (LDGSTS)
#define CP_ASYNC16(saddr, gptr) \
    asm volatile("cp.async.cg.shared.global [%0], [%1], 16;" :: "r"(saddr), "l"(gptr))
#define CP_COMMIT() asm volatile("cp.async.commit_group;" ::: "memory")
#define CP_WAIT(n)  asm volatile("cp.async.wait_group %0;" :: "n"(n) : "memory")

__device__ __forceinline__ float u64_lo(u64 v) { return __uint_as_float((unsigned)v); }
__device__ __forceinline__ float u64_hi(u64 v) { return __uint_as_float((unsigned)(v >> 32)); }

__device__ float g_DnT[NA * CM];
__device__ float g_Dn[CM * NA];
__device__ float g_G[NA * NA];
__device__ float g_H[(size_t)MS * NA];
__device__ float g_partial[1024];
__device__ unsigned g_count = 0;

// ---------------------------------------------------------------------------
// Kernel 1: normalize dictionary. 16 CTAs x 32-column tiles; smem-staged,
// all gmem traffic coalesced (R14 measured-best version).
// ---------------------------------------------------------------------------
__global__ __launch_bounds__(256) void k_norm(const float* __restrict__ dict) {
    __shared__ float T[CM][33];
    __shared__ float inv[32];
    const int n0 = blockIdx.x * 32;
    const int lane = threadIdx.x & 31;
    const int wid  = threadIdx.x >> 5;

    #pragma unroll
    for (int c = wid; c < CM; c += 8)
        T[c][lane] = dict[c * NA + n0 + lane];
    __syncthreads();

    if (threadIdx.x < 32) {
        float s = 0.f;
        #pragma unroll
        for (int c = 0; c < CM; c++) {
            float v = T[c][threadIdx.x];
            s += v * v;
        }
        inv[threadIdx.x] = 1.f / fmaxf(sqrtf(s), 1e-10f);
    }
    __syncthreads();

    #pragma unroll
    for (int c = wid; c < CM; c += 8)
        g_Dn[c * NA + n0 + lane] = T[c][lane] * inv[lane];

    #pragma unroll
    for (int x = wid; x < 32; x += 8) {
        float iv = inv[x];
        #pragma unroll
        for (int c = lane; c < CM; c += 32)
            g_DnT[(n0 + x) * CM + c] = T[c][x] * iv;
    }
}

// ---------------------------------------------------------------------------
// Kernel 2: FUSED  H = X^T Dn (bids 0..1023, cp.async double-buffered K=2x32)
//           and   G = Dn^T Dn (bids 1024..1087, tail-wave).
// ---------------------------------------------------------------------------
__global__ __launch_bounds__(256, 2) void k_gg(const float* __restrict__ ze) {
    __shared__ float S[4 * 32 * 128];   // 64KB: As0|As1|Bs0|Bs1

    if (blockIdx.x < 1024) {
        // ---------------- GEMM branch (pipelined) ----------------
        float (*As)[32][128] = (float (*)[32][128])S;
        float (*Bs)[32][128] = (float (*)[32][128])(S + 2 * 32 * 128);
        int tx = threadIdx.x & 15, ty = threadIdx.x >> 4;
        int m0 = (blockIdx.x >> 2) * 128, n0 = (blockIdx.x & 3) * 128;
        int bb = m0 >> 12;
        int p0 = m0 & (HW - 1);
        const float* zb = ze + (size_t)bb * CHW + p0;

        // issue both K-chunks via cp.async, one commit group each
        #pragma unroll
        for (int s = 0; s < 2; s++) {
            int c0 = s * 32;
            #pragma unroll
            for (int r = 0; r < 4; r++) {
                int idx = r * 256 + threadIdx.x;
                int kk = idx >> 5, m4 = (idx & 31) << 2;
                unsigned sa = (unsigned)__cvta_generic_to_shared(&As[s][kk][m4]);
                unsigned sb = (unsigned)__cvta_generic_to_shared(&Bs[s][kk][m4]);
                CP_ASYNC16(sa, zb + (size_t)(c0 + kk) * HW + m4);
                CP_ASYNC16(sb, g_Dn + (size_t)(c0 + kk) * NA + n0 + m4);
            }
            CP_COMMIT();
        }

        u64 acc2[8][4];
        #pragma unroll
        for (int i = 0; i < 8; i++)
            #pragma unroll
            for (int j = 0; j < 4; j++) acc2[i][j] = 0ull;

        #pragma unroll
        for (int s = 0; s < 2; s++) {
            if (s == 0) CP_WAIT(1); else CP_WAIT(0);
            __syncthreads();
            #pragma unroll
            for (int k = 0; k < 32; k++) {
                float4 a0 = *(float4*)&As[s][k][ty * 8];
                float4 a1 = *(float4*)&As[s][k][ty * 8 + 4];
                ulonglong2 bp0 = *(ulonglong2*)&Bs[s][k][tx * 8];
                ulonglong2 bp1 = *(ulonglong2*)&Bs[s][k][tx * 8 + 4];
                float ar[8] = {a0.x, a0.y, a0.z, a0.w, a1.x, a1.y, a1.z, a1.w};
                u64 bp[4] = {bp0.x, bp0.y, bp1.x, bp1.y};
                #pragma unroll
                for (int i = 0; i < 8; i++) {
                    u64 ad;
                    F32X2_DUP(ad, ar[i]);
                    #pragma unroll
                    for (int j = 0; j < 4; j++)
                        F32X2_FMA(acc2[i][j], ad, bp[j]);
                }
            }
        }
        #pragma unroll
        for (int i = 0; i < 8; i++) {
            int m = m0 + ty * 8 + i;
            u64* o = (u64*)&g_H[(size_t)m * NA + n0 + tx * 8];
            ulonglong2 s0, s1;
            s0.x = acc2[i][0]; s0.y = acc2[i][1];
            s1.x = acc2[i][2]; s1.y = acc2[i][3];
            *(ulonglong2*)o       = s0;
            *(ulonglong2*)(o + 2) = s1;
        }
    } else {
        // ---------------- GRAM branch ----------------
        int bid2 = blockIdx.x - 1024;
        float (*As)[64] = (float (*)[64])S;
        float (*Bs)[64] = (float (*)[64])(S + CM * 64);
        int i0 = (bid2 >> 3) * 64, j0 = (bid2 & 7) * 64;

        #pragma unroll
        for (int r = 0; r < 4; r++) {
            int idx = r * 256 + threadIdx.x;
            int c = idx >> 4, m4 = (idx & 15) << 2;
            *(float4*)&As[c][m4] = *(const float4*)(g_Dn + c * NA + i0 + m4);
            *(float4*)&Bs[c][m4] = *(const float4*)(g_Dn + c * NA + j0 + m4);
        }
        __syncthreads();

        int tx = threadIdx.x & 15, ty = threadIdx.x >> 4;
        u64 acc2[4][2];
        #pragma unroll
        for (int i = 0; i < 4; i++) { acc2[i][0] = 0ull; acc2[i][1] = 0ull; }

        #pragma unroll
        for (int k = 0; k < CM; k++) {
            float4 a = *(float4*)&As[k][ty * 4];
            ulonglong2 b = *(ulonglong2*)&Bs[k][tx * 4];
            float ar[4] = {a.x, a.y, a.z, a.w};
            #pragma unroll
            for (int i = 0; i < 4; i++) {
                u64 ad;
                F32X2_DUP(ad, ar[i]);
                F32X2_FMA(acc2[i][0], ad, b.x);
                F32X2_FMA(acc2[i][1], ad, b.y);
            }
        }
        #pragma unroll
        for (int i = 0; i < 4; i++) {
            ulonglong2 s;
            s.x = acc2[i][0]; s.y = acc2[i][1];
            *(ulonglong2*)&g_G[(size_t)(i0 + ty * 4 + i) * NA + j0 + tx * 4] = s;
        }
    }
}

// ---------------------------------------------------------------------------
// Kernel 3: OMP + coalesced reconstruction + last-CTA loss finalization.
// ---------------------------------------------------------------------------
__global__ __launch_bounds__(256, 3) void k_omp(const float* __restrict__ ze,
                                                float* __restrict__ out_zdl,
                                                float* __restrict__ out_sup,
                                                float* __restrict__ out_cf,
                                                float* __restrict__ out_loss) {
    __shared__ float rows[8][3][NA];   // 48KB; dead after OMP, reused as tile
    __shared__ unsigned isLast;

    const int lane = threadIdx.x & 31;
    const int wid  = threadIdx.x >> 5;
    const int bid  = gridDim.x - 1 - blockIdx.x;
    const int m0 = bid * 32;

    float recA[4], recB[4];

    #pragma unroll 1
    for (int it = 0; it < 4; it++) {
        const int m = m0 + wid * 4 + it;
        const float* Hb = g_H + (size_t)m * NA;
        const ulonglong2* Hb2 = (const ulonglong2*)Hb;

        u64   h2[8];
        float Lo[10];
        float Linv[5];
        float y[5];
        float gam[5];
        int   sel[5];

        float bv = 0.f;
#pragma unroll
        for (int j = 0; j < 4; j++) {
            ulonglong2 v = __ldg(&Hb2[lane + 32 * j]);
            h2[2 * j] = v.x;
            h2[2 * j + 1] = v.y;
            bv = fmaxf(bv, fabsf(u64_lo(v.x)));
            bv = fmaxf(bv, fabsf(u64_hi(v.x)));
            bv = fmaxf(bv, fabsf(u64_lo(v.y)));
            bv = fmaxf(bv, fabsf(u64_hi(v.y)));
        }

#pragma unroll
        for (int k = 1; k <= KS; k++) {
            float wmax = __uint_as_float(__reduce_max_sync(FULL, __float_as_uint(bv)));
            int cand = 1 << 30;
#pragma unroll
            for (int j = 3; j >= 0; j--) {
                int base = 4 * (lane + 32 * j);
                u64 px = h2[2 * j], py = h2[2 * j + 1];
                if (fabsf(u64_hi(py)) == wmax) cand = base + 3;
                if (fabsf(u64_lo(py)) == wmax) cand = base + 2;
                if (fabsf(u64_hi(px)) == wmax) cand = base + 1;
                if (fabsf(u64_lo(px)) == wmax) cand = base;
            }
            int bi = __reduce_min_sync(FULL, cand);

            const float* Grow = g_G + (size_t)bi * NA;

            ulonglong2 gvv[4];
            if (k < KS) {
                const ulonglong2* Gr2 = (const ulonglong2*)Grow;
#pragma unroll
                for (int j = 0; j < 4; j++) gvv[j] = __ldg(&Gr2[lane + 32 * j]);
            }

            float hbv = __ldg(Hb + bi);

            float Gv[4];
#pragma unroll
            for (int t = 0; t < 3; t++)
                if (t < k - 1) Gv[t] = rows[wid][t][bi];
            if (k == KS) Gv[3] = __ldg(g_G + (size_t)sel[3] * NA + bi);

            if (k > 1) {
                float w[4], ww = 0.f;
#pragma unroll
                for (int i = 0; i < 4; i++) {
                    if (i < k - 1) {
                        float a = Gv[i];
#pragma unroll
                        for (int j = 0; j < 4; j++)
                            if (j < i) a -= Lo[(i - 1) * i / 2 + j] * w[j];
                        if (i > 0) a *= Linv[i];
                        w[i] = a;
                        ww += a * a;
                    }
                }
                const int r = k - 1;
#pragma unroll
                for (int j = 0; j < 4; j++)
                    if (j < r) Lo[(r - 1) * r / 2 + j] = w[j];
                Linv[r] = rsqrtf(fmaxf(1.f - ww, 1e-12f));
            } else {
                Linv[0] = 1.f;
            }
            sel[k - 1] = bi;

            {
                const int i = k - 1;
                float a = hbv;
#pragma unroll
                for (int j = 0; j < 4; j++)
                    if (j < i) a -= Lo[(i - 1) * i / 2 + j] * y[j];
                y[i] = a * Linv[i];
            }

            float g2[5];
#pragma unroll
            for (int i = 4; i >= 0; i--) {
                if (i < k) {
                    float a = y[i];
#pragma unroll
                    for (int j = 0; j < 5; j++)
                        if (j > i && j < k) a -= Lo[(j - 1) * j / 2 + i] * g2[j];
                    g2[i] = a * Linv[i];
                }
            }
            float dg[5];
#pragma unroll
            for (int i = 0; i < 5; i++) {
                if (i < k) {
                    float old = (i < k - 1) ? gam[i] : 0.f;
                    dg[i] = g2[i] - old;
                    gam[i] = g2[i];
                }
            }

            if (k < KS) {
                u64 ndp[4];
#pragma unroll
                for (int t = 0; t < 4; t++)
                    if (t < k) F32X2_DUP(ndp[t], -dg[t]);
                bv = 0.f;
#pragma unroll
                for (int j = 0; j < 4; j++) {
                    int fi = 4 * (lane + 32 * j);
                    if (k - 1 < 3)
                        *(ulonglong2*)&rows[wid][k - 1 < 3 ? k - 1 : 0][fi] = gvv[j];
                    u64 a0, a1;
                    F32X2_MUL(a0, ndp[k - 1], gvv[j].x);
                    F32X2_MUL(a1, ndp[k - 1], gvv[j].y);
#pragma unroll
                    for (int t = 0; t < 3; t++) {
                        if (t < k - 1) {
                            ulonglong2 rv = *(const ulonglong2*)&rows[wid][t][fi];
                            F32X2_FMA(a0, ndp[t], rv.x);
                            F32X2_FMA(a1, ndp[t], rv.y);
                        }
                    }
                    u64 hn0, hn1;
                    F32X2_ADD(hn0, h2[2 * j], a0);
                    F32X2_ADD(hn1, h2[2 * j + 1], a1);
                    h2[2 * j] = hn0;
                    h2[2 * j + 1] = hn1;
                    bv = fmaxf(bv, fabsf(u64_lo(hn0)));
                    bv = fmaxf(bv, fabsf(u64_hi(hn0)));
                    bv = fmaxf(bv, fabsf(u64_lo(hn1)));
                    bv = fmaxf(bv, fabsf(u64_hi(hn1)));
                }
            }
        }

        if (lane < KS) {
            float s = (lane == 0) ? (float)sel[0] :
                      (lane == 1) ? (float)sel[1] :
                      (lane == 2) ? (float)sel[2] :
                      (lane == 3) ? (float)sel[3] : (float)sel[4];
            float c = (lane == 0) ? gam[0] :
                      (lane == 1) ? gam[1] :
                      (lane == 2) ? gam[2] :
                      (lane == 3) ? gam[3] : gam[4];
            out_sup[(size_t)m * KS + lane] = s;
            out_cf[(size_t)m * KS + lane]  = c;
        }

        {
            float r0 = 0.f, r1 = 0.f;
#pragma unroll
            for (int t = 0; t < KS; t++) {
                const float* dn = g_DnT + sel[t] * CM;
                r0 = fmaf(gam[t], __ldg(dn + lane), r0);
                r1 = fmaf(gam[t], __ldg(dn + lane + 32), r1);
            }
            recA[it] = r0;
            recB[it] = r1;
        }
    }

    // ---- alias the dead rows cache as transpose tile + reduction scratch
    __syncthreads();
    float* sm = &rows[0][0][0];
    float (*tile)[33] = (float (*)[33])sm;
    float* red = sm + CM * 33;
#pragma unroll
    for (int it = 0; it < 4; it++) {
        int s = wid * 4 + it;
        tile[lane][s]      = recA[it];
        tile[lane + 32][s] = recB[it];
    }
    __syncthreads();

    int b  = m0 >> 12;
    int p0 = m0 & (HW - 1);
    int p  = threadIdx.x & 31;
    int cb = threadIdx.x >> 5;
    float err = 0.f;
#pragma unroll
    for (int j = 0; j < 8; j++) {
        int c = cb * 8 + j;
        size_t zi = (size_t)b * CHW + (size_t)c * HW + p0 + p;
        float r = tile[c][p];
        float x = ze[zi];
        float d = r - x;
        err += d * d;
        out_zdl[zi] = r;
    }
    red[threadIdx.x] = err;
    __syncthreads();
    for (int o = 128; o; o >>= 1) {
        if (threadIdx.x < o) red[threadIdx.x] += red[threadIdx.x + o];
        __syncthreads();
    }
    if (threadIdx.x == 0) g_partial[bid] = red[0];

    // ---- last CTA finalizes the loss (deterministic order)
    __threadfence();
    if (threadIdx.x == 0)
        isLast = (atomicAdd(&g_count, 1u) == gridDim.x - 1) ? 1u : 0u;
    __syncthreads();
    if (isLast) {
        float s = 0.f;
        for (int i = threadIdx.x; i < 1024; i += 256) s += g_partial[i];
        red[threadIdx.x] = s;
        __syncthreads();
        for (int o = 128; o; o >>= 1) {
            if (threadIdx.x < o) red[threadIdx.x] += red[threadIdx.x + o];
            __syncthreads();
        }
        if (threadIdx.x == 0) {
            out_loss[0] = 1.25f * red[0] / NUMEL;
            g_count = 0;
        }
    }
}

// ---------------------------------------------------------------------------
extern "C" void kernel_launch(void* const* d_in, const int* in_sizes, int n_in,
                              void* d_out, int out_size) {
    const float* ze   = (const float*)d_in[0];
    const float* dict = (const float*)d_in[1];
    float* out = (float*)d_out;
    float* out_zdl  = out;
    float* out_loss = out + 2097152;
    float* out_sup  = out + 2097153;
    float* out_cf   = out + 2097153 + 163840;

    k_norm<<<16, 256>>>(dict);
    k_gg<<<1024 + 64, 256>>>(ze);
    k_omp<<<MS / 32, 256>>>(ze, out_zdl, out_sup, out_cf, out_loss);
}